// round 8
// baseline (speedup 1.0000x reference)
#include <cuda_runtime.h>
#include <cuda_fp16.h>

#define NB 2048
#define NF 4096
#define NC 8192
#define NT 8
#define NK 1024
#define NS 8
#define MB 8            // batch rows per CTA (fp16, 8 rows per 16B slot)
#define THREADS 1024    // one k per thread (R6 config — best so far)

// 16-bit slot table, layout [s][k][t]: index = (s*NK + k)*NT + t.
// slot = feat*2 + (sign>0 ? 0 : 1); smem byte addr = slot*16.
__device__ unsigned short g_slot[NS * NK * NT];   // 128 KB

__global__ void prep_kernel(const int* __restrict__ conj_feat,
                            const int* __restrict__ conj_sign,
                            const int* __restrict__ class_conj) {
    int i = blockIdx.x * blockDim.x + threadIdx.x;
    if (i >= NK * NS * NT) return;
    int k = i >> 6;
    int j = i & 63;
    int s = j >> 3;
    int t = j & 7;
    int c    = class_conj[k * NS + s];
    int feat = conj_feat[c * NT + t];
    int sign = conj_sign[c * NT + t];
    g_slot[(s * NK + k) * NT + t] = (unsigned short)(feat * 2 + (sign > 0 ? 0 : 1));
}

// Conflict shaping: for each (s, warp-of-32-k), permute each lane's 8 slots
// across the 8 LDS steps so that per-step bank-group (slot & 7) load is
// balanced. Product over t is commutative, so any per-(k,s) permutation is
// correct. One thread per (s, warp): 8 * 32 = 256 units, one-time cost.
__global__ void shape_kernel() {
    int i = blockIdx.x * blockDim.x + threadIdx.x;
    if (i >= NS * (NK / 32)) return;
    int s = i / (NK / 32);
    int w = i % (NK / 32);

    int cnt[8][8];                       // [step][bank group]
    #pragma unroll
    for (int a = 0; a < 8; a++)
        #pragma unroll
        for (int b = 0; b < 8; b++) cnt[a][b] = 0;

    for (int lane = 0; lane < 32; lane++) {
        unsigned short* base = &g_slot[((size_t)s * NK + w * 32 + lane) * NT];
        unsigned short sl[8], perm[8];
        bool used[8] = {false,false,false,false,false,false,false,false};
        #pragma unroll
        for (int t = 0; t < 8; t++) sl[t] = base[t];
        // greedily place each slot into the unused step whose group-load is lowest
        #pragma unroll
        for (int t = 0; t < 8; t++) {
            int g = sl[t] & 7;
            int best = -1, bc = 1 << 30;
            #pragma unroll
            for (int st = 0; st < 8; st++)
                if (!used[st] && cnt[st][g] < bc) { bc = cnt[st][g]; best = st; }
            used[best] = true;
            cnt[best][g]++;
            perm[best] = sl[t];
        }
        #pragma unroll
        for (int t = 0; t < 8; t++) base[t] = perm[t];
    }
}

static __device__ __forceinline__ unsigned hmul2u(unsigned a, unsigned b) {
    __half2 ha = *reinterpret_cast<__half2*>(&a);
    __half2 hb = *reinterpret_cast<__half2*>(&b);
    __half2 hr = __hmul2(ha, hb);
    return *reinterpret_cast<unsigned*>(&hr);
}
static __device__ __forceinline__ unsigned hmax2u(unsigned a, unsigned b) {
    __half2 ha = *reinterpret_cast<__half2*>(&a);
    __half2 hb = *reinterpret_cast<__half2*>(&b);
    __half2 hr = __hmax2(ha, hb);
    return *reinterpret_cast<unsigned*>(&hr);
}
static __device__ __forceinline__ uint4 mulh8(uint4 a, uint4 b) {
    a.x = hmul2u(a.x, b.x); a.y = hmul2u(a.y, b.y);
    a.z = hmul2u(a.z, b.z); a.w = hmul2u(a.w, b.w);
    return a;
}
static __device__ __forceinline__ uint4 maxh8(uint4 a, uint4 b) {
    a.x = hmax2u(a.x, b.x); a.y = hmax2u(a.y, b.y);
    a.z = hmax2u(a.z, b.z); a.w = hmax2u(a.w, b.w);
    return a;
}
static __device__ __forceinline__ unsigned pack2(float a, float b) {
    __half2 h = __floats2half2_rn(a, b);
    return *reinterpret_cast<unsigned*>(&h);
}

__global__ void __launch_bounds__(THREADS, 1)
dnf_kernel(const float* __restrict__ x, float* __restrict__ out) {
    extern __shared__ unsigned smem_u[];   // [4096 feat][2 var][4 x u32] = 128 KB
    const int b0 = blockIdx.x * MB;

    // Phase A: build 16B slots, conflict-free STS.128, coalesced LDG.
    uint4* slots = (uint4*)smem_u;
    for (int f = threadIdx.x; f < NF; f += THREADS) {
        float v[MB];
        #pragma unroll
        for (int r = 0; r < MB; r++)
            v[r] = x[(size_t)(b0 + r) * NF + f];
        uint4 hx, hn;
        hx.x = pack2(v[0], v[1]);               hn.x = pack2(1.f - v[0], 1.f - v[1]);
        hx.y = pack2(v[2], v[3]);               hn.y = pack2(1.f - v[2], 1.f - v[3]);
        hx.z = pack2(v[4], v[5]);               hn.z = pack2(1.f - v[4], 1.f - v[5]);
        hx.w = pack2(v[6], v[7]);               hn.w = pack2(1.f - v[6], 1.f - v[7]);
        slots[f * 2]     = hx;
        slots[f * 2 + 1] = hn;
    }
    __syncthreads();

    const char* sb = (const char*)smem_u;
    const int k = threadIdx.x;                       // NK == THREADS
    const uint4* tab = (const uint4*)g_slot + k;     // tab[s*NK]

    uint4 ta = tab[0];                               // s   table
    uint4 tb = tab[NK];                              // s+1 table
    uint4 mx = make_uint4(0u, 0u, 0u, 0u);           // fp16 products >= 0

    #pragma unroll
    for (int s = 0; s < NS; s++) {
        int spre = s + 2 < NS - 1 ? s + 2 : NS - 1;
        uint4 tn = tab[spre * NK];

        // step order matters: LDS j uses each lane's shaped slot for step j
        uint4 q0 = *(const uint4*)(sb + ((ta.x & 0xFFFFu) << 4));
        uint4 q1 = *(const uint4*)(sb + ((ta.x >> 16)     << 4));
        uint4 q2 = *(const uint4*)(sb + ((ta.y & 0xFFFFu) << 4));
        uint4 q3 = *(const uint4*)(sb + ((ta.y >> 16)     << 4));
        uint4 q4 = *(const uint4*)(sb + ((ta.z & 0xFFFFu) << 4));
        uint4 q5 = *(const uint4*)(sb + ((ta.z >> 16)     << 4));
        uint4 q6 = *(const uint4*)(sb + ((ta.w & 0xFFFFu) << 4));
        uint4 q7 = *(const uint4*)(sb + ((ta.w >> 16)     << 4));

        uint4 p = mulh8(mulh8(mulh8(q0, q1), mulh8(q2, q3)),
                        mulh8(mulh8(q4, q5), mulh8(q6, q7)));
        mx = maxh8(mx, p);
        ta = tb;
        tb = tn;
    }

    float2 r01 = __half22float2(*reinterpret_cast<__half2*>(&mx.x));
    float2 r23 = __half22float2(*reinterpret_cast<__half2*>(&mx.y));
    float2 r45 = __half22float2(*reinterpret_cast<__half2*>(&mx.z));
    float2 r67 = __half22float2(*reinterpret_cast<__half2*>(&mx.w));
    out[(size_t)(b0 + 0) * NK + k] = r01.x;
    out[(size_t)(b0 + 1) * NK + k] = r01.y;
    out[(size_t)(b0 + 2) * NK + k] = r23.x;
    out[(size_t)(b0 + 3) * NK + k] = r23.y;
    out[(size_t)(b0 + 4) * NK + k] = r45.x;
    out[(size_t)(b0 + 5) * NK + k] = r45.y;
    out[(size_t)(b0 + 6) * NK + k] = r67.x;
    out[(size_t)(b0 + 7) * NK + k] = r67.y;
}

extern "C" void kernel_launch(void* const* d_in, const int* in_sizes, int n_in,
                              void* d_out, int out_size) {
    const float* x  = (const float*)d_in[0];
    const int*   cf = (const int*)d_in[1];
    const int*   cs = (const int*)d_in[2];
    const int*   cc = (const int*)d_in[3];
    float* out = (float*)d_out;

    prep_kernel<<<(NK * NS * NT + 255) / 256, 256>>>(cf, cs, cc);
    shape_kernel<<<1, 256>>>();

    size_t smem_bytes = (size_t)NF * 2 * MB * sizeof(__half);  // 131072
    cudaFuncSetAttribute(dnf_kernel,
                         cudaFuncAttributeMaxDynamicSharedMemorySize,
                         (int)smem_bytes);
    dnf_kernel<<<NB / MB, THREADS, smem_bytes>>>(x, out);
}

// round 9
// speedup vs baseline: 6.0162x; 6.0162x over previous
#include <cuda_runtime.h>
#include <cuda_fp16.h>

#define NB 2048
#define NF 4096
#define NC 8192
#define NT 8
#define NK 1024
#define NS 8
#define MB 8            // batch rows per CTA (fp16, 8 rows per 16B slot)
#define THREADS 1024    // one k per thread

// 16-bit slot table, layout [s][k][t]: index = (s*NK + k)*NT + t.
// slot = feat*2 + (sign>0 ? 0 : 1); smem byte addr = slot*16.
__device__ unsigned short g_slot[NS * NK * NT];   // 128 KB

// One thread per (k,s): vectorized conjunction fetch + single STG.128.
__global__ void prep_kernel(const int* __restrict__ conj_feat,
                            const int* __restrict__ conj_sign,
                            const int* __restrict__ class_conj) {
    int i = blockIdx.x * blockDim.x + threadIdx.x;   // i = s*NK + k (k fast)
    if (i >= NS * NK) return;
    int s = i >> 10;
    int k = i & (NK - 1);
    int c = class_conj[k * NS + s];

    const int4* fp = (const int4*)(conj_feat + (size_t)c * NT);
    const int4* sp = (const int4*)(conj_sign + (size_t)c * NT);
    int4 f0 = fp[0], f1 = fp[1];
    int4 s0 = sp[0], s1 = sp[1];

    uint4 w;
    w.x = (unsigned)(f0.x * 2 + (s0.x > 0 ? 0 : 1))
        | ((unsigned)(f0.y * 2 + (s0.y > 0 ? 0 : 1)) << 16);
    w.y = (unsigned)(f0.z * 2 + (s0.z > 0 ? 0 : 1))
        | ((unsigned)(f0.w * 2 + (s0.w > 0 ? 0 : 1)) << 16);
    w.z = (unsigned)(f1.x * 2 + (s1.x > 0 ? 0 : 1))
        | ((unsigned)(f1.y * 2 + (s1.y > 0 ? 0 : 1)) << 16);
    w.w = (unsigned)(f1.z * 2 + (s1.z > 0 ? 0 : 1))
        | ((unsigned)(f1.w * 2 + (s1.w > 0 ? 0 : 1)) << 16);

    ((uint4*)g_slot)[i] = w;   // coalesced: consecutive k -> consecutive 16B
}

static __device__ __forceinline__ unsigned hmul2u(unsigned a, unsigned b) {
    __half2 ha = *reinterpret_cast<__half2*>(&a);
    __half2 hb = *reinterpret_cast<__half2*>(&b);
    __half2 hr = __hmul2(ha, hb);
    return *reinterpret_cast<unsigned*>(&hr);
}
static __device__ __forceinline__ unsigned hmax2u(unsigned a, unsigned b) {
    __half2 ha = *reinterpret_cast<__half2*>(&a);
    __half2 hb = *reinterpret_cast<__half2*>(&b);
    __half2 hr = __hmax2(ha, hb);
    return *reinterpret_cast<unsigned*>(&hr);
}
static __device__ __forceinline__ uint4 mulh8(uint4 a, uint4 b) {
    a.x = hmul2u(a.x, b.x); a.y = hmul2u(a.y, b.y);
    a.z = hmul2u(a.z, b.z); a.w = hmul2u(a.w, b.w);
    return a;
}
static __device__ __forceinline__ uint4 maxh8(uint4 a, uint4 b) {
    a.x = hmax2u(a.x, b.x); a.y = hmax2u(a.y, b.y);
    a.z = hmax2u(a.z, b.z); a.w = hmax2u(a.w, b.w);
    return a;
}
static __device__ __forceinline__ unsigned pack2(float a, float b) {
    __half2 h = __floats2half2_rn(a, b);
    return *reinterpret_cast<unsigned*>(&h);
}

__global__ void __launch_bounds__(THREADS, 1)
dnf_kernel(const float* __restrict__ x, float* __restrict__ out) {
    extern __shared__ unsigned smem_u[];   // [4096 feat][2 var][4 x u32] = 128 KB
    const int b0 = blockIdx.x * MB;

    // Phase A: each thread owns 4 consecutive feats; 8 LDG.128 (deep MLP)
    // then 8 conflict-free STS.128. Exactly one pass: 1024 thr * 4 = 4096.
    uint4* slots = (uint4*)smem_u;
    {
        const int f0 = threadIdx.x * 4;
        float4 vr[MB];
        #pragma unroll
        for (int r = 0; r < MB; r++)
            vr[r] = *(const float4*)&x[(size_t)(b0 + r) * NF + f0];
        #pragma unroll
        for (int j = 0; j < 4; j++) {
            float v[MB];
            #pragma unroll
            for (int r = 0; r < MB; r++)
                v[r] = j == 0 ? vr[r].x : j == 1 ? vr[r].y : j == 2 ? vr[r].z : vr[r].w;
            uint4 hx, hn;
            hx.x = pack2(v[0], v[1]);           hn.x = pack2(1.f - v[0], 1.f - v[1]);
            hx.y = pack2(v[2], v[3]);           hn.y = pack2(1.f - v[2], 1.f - v[3]);
            hx.z = pack2(v[4], v[5]);           hn.z = pack2(1.f - v[4], 1.f - v[5]);
            hx.w = pack2(v[6], v[7]);           hn.w = pack2(1.f - v[6], 1.f - v[7]);
            slots[(f0 + j) * 2]     = hx;
            slots[(f0 + j) * 2 + 1] = hn;
        }
    }
    __syncthreads();

    const char* sb = (const char*)smem_u;
    const int k = threadIdx.x;                       // NK == THREADS
    const uint4* tab = (const uint4*)g_slot + k;     // tab[s*NK]

    uint4 ta = tab[0];                               // s   table
    uint4 tb = tab[NK];                              // s+1 table
    uint4 mx = make_uint4(0u, 0u, 0u, 0u);           // fp16 products >= 0

    #pragma unroll
    for (int s = 0; s < NS; s++) {
        int spre = s + 2 < NS - 1 ? s + 2 : NS - 1;  // prefetch s+2 (clamped)
        uint4 tn = tab[spre * NK];

        uint4 q0 = *(const uint4*)(sb + ((ta.x & 0xFFFFu) << 4));
        uint4 q1 = *(const uint4*)(sb + ((ta.x >> 16)     << 4));
        uint4 q2 = *(const uint4*)(sb + ((ta.y & 0xFFFFu) << 4));
        uint4 q3 = *(const uint4*)(sb + ((ta.y >> 16)     << 4));
        uint4 q4 = *(const uint4*)(sb + ((ta.z & 0xFFFFu) << 4));
        uint4 q5 = *(const uint4*)(sb + ((ta.z >> 16)     << 4));
        uint4 q6 = *(const uint4*)(sb + ((ta.w & 0xFFFFu) << 4));
        uint4 q7 = *(const uint4*)(sb + ((ta.w >> 16)     << 4));

        uint4 p = mulh8(mulh8(mulh8(q0, q1), mulh8(q2, q3)),
                        mulh8(mulh8(q4, q5), mulh8(q6, q7)));
        mx = maxh8(mx, p);
        ta = tb;
        tb = tn;
    }

    float2 r01 = __half22float2(*reinterpret_cast<__half2*>(&mx.x));
    float2 r23 = __half22float2(*reinterpret_cast<__half2*>(&mx.y));
    float2 r45 = __half22float2(*reinterpret_cast<__half2*>(&mx.z));
    float2 r67 = __half22float2(*reinterpret_cast<__half2*>(&mx.w));
    out[(size_t)(b0 + 0) * NK + k] = r01.x;
    out[(size_t)(b0 + 1) * NK + k] = r01.y;
    out[(size_t)(b0 + 2) * NK + k] = r23.x;
    out[(size_t)(b0 + 3) * NK + k] = r23.y;
    out[(size_t)(b0 + 4) * NK + k] = r45.x;
    out[(size_t)(b0 + 5) * NK + k] = r45.y;
    out[(size_t)(b0 + 6) * NK + k] = r67.x;
    out[(size_t)(b0 + 7) * NK + k] = r67.y;
}

extern "C" void kernel_launch(void* const* d_in, const int* in_sizes, int n_in,
                              void* d_out, int out_size) {
    const float* x  = (const float*)d_in[0];
    const int*   cf = (const int*)d_in[1];
    const int*   cs = (const int*)d_in[2];
    const int*   cc = (const int*)d_in[3];
    float* out = (float*)d_out;

    prep_kernel<<<(NS * NK + 255) / 256, 256>>>(cf, cs, cc);

    size_t smem_bytes = (size_t)NF * 2 * MB * sizeof(__half);  // 131072
    cudaFuncSetAttribute(dnf_kernel,
                         cudaFuncAttributeMaxDynamicSharedMemorySize,
                         (int)smem_bytes);
    dnf_kernel<<<NB / MB, THREADS, smem_bytes>>>(x, out);
}

// round 10
// speedup vs baseline: 7.1818x; 1.1938x over previous
#include <cuda_runtime.h>
#include <cuda_fp16.h>

#define NB 2048
#define NF 4096
#define NC 8192
#define NT 8
#define NK 1024
#define NS 8
#define MB 8            // batch rows per CTA (fp16, 8 rows per 16B slot)
#define THREADS 1024    // one k per thread

// 16-bit slot table, layout [s][k][t]: index = (s*NK + k)*NT + t.
// slot = feat + (sign>0 ? 0 : 4096); smem byte addr = slot*16.
// smem layout: variant 0 (x) at [0,64K), variant 1 (1-x) at [64K,128K),
// within a variant: [feat][8 rows] fp16 = 16 B per feat.
__device__ unsigned short g_slot[NS * NK * NT];   // 128 KB

// One thread per (k,s): vectorized conjunction fetch + single STG.128.
__global__ void prep_kernel(const int* __restrict__ conj_feat,
                            const int* __restrict__ conj_sign,
                            const int* __restrict__ class_conj) {
    int i = blockIdx.x * blockDim.x + threadIdx.x;   // i = s*NK + k (k fast)
    if (i >= NS * NK) return;
    int s = i >> 10;
    int k = i & (NK - 1);
    int c = class_conj[k * NS + s];

    const int4* fp = (const int4*)(conj_feat + (size_t)c * NT);
    const int4* sp = (const int4*)(conj_sign + (size_t)c * NT);
    int4 f0 = fp[0], f1 = fp[1];
    int4 s0 = sp[0], s1 = sp[1];

    uint4 w;
    w.x = (unsigned)(f0.x + (s0.x > 0 ? 0 : 4096))
        | ((unsigned)(f0.y + (s0.y > 0 ? 0 : 4096)) << 16);
    w.y = (unsigned)(f0.z + (s0.z > 0 ? 0 : 4096))
        | ((unsigned)(f0.w + (s0.w > 0 ? 0 : 4096)) << 16);
    w.z = (unsigned)(f1.x + (s1.x > 0 ? 0 : 4096))
        | ((unsigned)(f1.y + (s1.y > 0 ? 0 : 4096)) << 16);
    w.w = (unsigned)(f1.z + (s1.z > 0 ? 0 : 4096))
        | ((unsigned)(f1.w + (s1.w > 0 ? 0 : 4096)) << 16);

    ((uint4*)g_slot)[i] = w;   // coalesced: consecutive k -> consecutive 16B
}

static __device__ __forceinline__ unsigned hmul2u(unsigned a, unsigned b) {
    __half2 ha = *reinterpret_cast<__half2*>(&a);
    __half2 hb = *reinterpret_cast<__half2*>(&b);
    __half2 hr = __hmul2(ha, hb);
    return *reinterpret_cast<unsigned*>(&hr);
}
static __device__ __forceinline__ unsigned hmax2u(unsigned a, unsigned b) {
    __half2 ha = *reinterpret_cast<__half2*>(&a);
    __half2 hb = *reinterpret_cast<__half2*>(&b);
    __half2 hr = __hmax2(ha, hb);
    return *reinterpret_cast<unsigned*>(&hr);
}
static __device__ __forceinline__ uint4 mulh8(uint4 a, uint4 b) {
    a.x = hmul2u(a.x, b.x); a.y = hmul2u(a.y, b.y);
    a.z = hmul2u(a.z, b.z); a.w = hmul2u(a.w, b.w);
    return a;
}
static __device__ __forceinline__ uint4 maxh8(uint4 a, uint4 b) {
    a.x = hmax2u(a.x, b.x); a.y = hmax2u(a.y, b.y);
    a.z = hmax2u(a.z, b.z); a.w = hmax2u(a.w, b.w);
    return a;
}
static __device__ __forceinline__ unsigned pack2(float a, float b) {
    __half2 h = __floats2half2_rn(a, b);
    return *reinterpret_cast<unsigned*>(&h);
}

__global__ void __launch_bounds__(THREADS, 1)
dnf_kernel(const float* __restrict__ x, float* __restrict__ out) {
    extern __shared__ unsigned smem_u[];   // 128 KB: [2 var][4096 feat][4 u32]
    const int b0 = blockIdx.x * MB;

    // Phase A: R6 mapping (f = tid, stride THREADS -> scalar coalesced LDG),
    // split-variant layout -> both STS.128 are conflict-free (16B lane stride).
    uint4* slots = (uint4*)smem_u;
    for (int f = threadIdx.x; f < NF; f += THREADS) {
        float v[MB];
        #pragma unroll
        for (int r = 0; r < MB; r++)
            v[r] = x[(size_t)(b0 + r) * NF + f];
        uint4 hx, hn;
        hx.x = pack2(v[0], v[1]);               hn.x = pack2(1.f - v[0], 1.f - v[1]);
        hx.y = pack2(v[2], v[3]);               hn.y = pack2(1.f - v[2], 1.f - v[3]);
        hx.z = pack2(v[4], v[5]);               hn.z = pack2(1.f - v[4], 1.f - v[5]);
        hx.w = pack2(v[6], v[7]);               hn.w = pack2(1.f - v[6], 1.f - v[7]);
        slots[f]        = hx;                   // variant 0: x
        slots[NF + f]   = hn;                   // variant 1: 1-x
    }
    __syncthreads();

    const char* sb = (const char*)smem_u;
    const int k = threadIdx.x;                       // NK == THREADS
    const uint4* tab = (const uint4*)g_slot + k;     // tab[s*NK]

    uint4 ta = tab[0];                               // s   table
    uint4 tb = tab[NK];                              // s+1 table
    uint4 mx = make_uint4(0u, 0u, 0u, 0u);           // fp16 products >= 0

    #pragma unroll
    for (int s = 0; s < NS; s++) {
        int spre = s + 2 < NS - 1 ? s + 2 : NS - 1;  // prefetch s+2 (clamped)
        uint4 tn = tab[spre * NK];

        uint4 q0 = *(const uint4*)(sb + ((ta.x & 0xFFFFu) << 4));
        uint4 q1 = *(const uint4*)(sb + ((ta.x >> 16)     << 4));
        uint4 q2 = *(const uint4*)(sb + ((ta.y & 0xFFFFu) << 4));
        uint4 q3 = *(const uint4*)(sb + ((ta.y >> 16)     << 4));
        uint4 q4 = *(const uint4*)(sb + ((ta.z & 0xFFFFu) << 4));
        uint4 q5 = *(const uint4*)(sb + ((ta.z >> 16)     << 4));
        uint4 q6 = *(const uint4*)(sb + ((ta.w & 0xFFFFu) << 4));
        uint4 q7 = *(const uint4*)(sb + ((ta.w >> 16)     << 4));

        uint4 p = mulh8(mulh8(mulh8(q0, q1), mulh8(q2, q3)),
                        mulh8(mulh8(q4, q5), mulh8(q6, q7)));
        mx = maxh8(mx, p);
        ta = tb;
        tb = tn;
    }

    float2 r01 = __half22float2(*reinterpret_cast<__half2*>(&mx.x));
    float2 r23 = __half22float2(*reinterpret_cast<__half2*>(&mx.y));
    float2 r45 = __half22float2(*reinterpret_cast<__half2*>(&mx.z));
    float2 r67 = __half22float2(*reinterpret_cast<__half2*>(&mx.w));
    out[(size_t)(b0 + 0) * NK + k] = r01.x;
    out[(size_t)(b0 + 1) * NK + k] = r01.y;
    out[(size_t)(b0 + 2) * NK + k] = r23.x;
    out[(size_t)(b0 + 3) * NK + k] = r23.y;
    out[(size_t)(b0 + 4) * NK + k] = r45.x;
    out[(size_t)(b0 + 5) * NK + k] = r45.y;
    out[(size_t)(b0 + 6) * NK + k] = r67.x;
    out[(size_t)(b0 + 7) * NK + k] = r67.y;
}

extern "C" void kernel_launch(void* const* d_in, const int* in_sizes, int n_in,
                              void* d_out, int out_size) {
    const float* x  = (const float*)d_in[0];
    const int*   cf = (const int*)d_in[1];
    const int*   cs = (const int*)d_in[2];
    const int*   cc = (const int*)d_in[3];
    float* out = (float*)d_out;

    prep_kernel<<<(NS * NK + 255) / 256, 256>>>(cf, cs, cc);

    size_t smem_bytes = (size_t)NF * 2 * MB * sizeof(__half);  // 131072
    cudaFuncSetAttribute(dnf_kernel,
                         cudaFuncAttributeMaxDynamicSharedMemorySize,
                         (int)smem_bytes);
    dnf_kernel<<<NB / MB, THREADS, smem_bytes>>>(x, out);
}

// round 11
// speedup vs baseline: 7.6302x; 1.0624x over previous
#include <cuda_runtime.h>
#include <cuda_fp16.h>

#define NB 2048
#define NF 4096
#define NC 8192
#define NT 8
#define NK 1024
#define NS 8
#define MB 8            // batch rows per CTA (fp16, 8 rows per 16B slot)
#define THREADS 1024    // one k per thread

// 16-bit slot table, layout [s][k][t]: index = (s*NK + k)*NT + t.
// slot = feat + (sign>0 ? 0 : 4096); smem byte addr = slot*16.
// smem: variant 0 (x) at [0,64K), variant 1 (1-x) at [64K,128K).
// Slots within each (k,s) group are SHAPED: sorted by bank group (slot&7)
// and rotated by k&7, so each LDS step across a warp sees a stratified
// bank-group mix instead of iid random (fewer conflict phases).
__device__ unsigned short g_slot[NS * NK * NT];   // 128 KB

__global__ void prep_kernel(const int* __restrict__ conj_feat,
                            const int* __restrict__ conj_sign,
                            const int* __restrict__ class_conj) {
    int i = blockIdx.x * blockDim.x + threadIdx.x;   // i = s*NK + k (k fast)
    if (i >= NS * NK) return;
    int s = i >> 10;
    int k = i & (NK - 1);
    int c = class_conj[k * NS + s];

    const int4* fp = (const int4*)(conj_feat + (size_t)c * NT);
    const int4* sp = (const int4*)(conj_sign + (size_t)c * NT);
    int4 f0 = fp[0], f1 = fp[1];
    int4 s0 = sp[0], s1 = sp[1];

    unsigned a[8];
    a[0] = (unsigned)(f0.x + (s0.x > 0 ? 0 : 4096));
    a[1] = (unsigned)(f0.y + (s0.y > 0 ? 0 : 4096));
    a[2] = (unsigned)(f0.z + (s0.z > 0 ? 0 : 4096));
    a[3] = (unsigned)(f0.w + (s0.w > 0 ? 0 : 4096));
    a[4] = (unsigned)(f1.x + (s1.x > 0 ? 0 : 4096));
    a[5] = (unsigned)(f1.y + (s1.y > 0 ? 0 : 4096));
    a[6] = (unsigned)(f1.z + (s1.z > 0 ? 0 : 4096));
    a[7] = (unsigned)(f1.w + (s1.w > 0 ? 0 : 4096));

    // Batcher odd-even sort by bank group (slot & 7); static indices only.
#define CSWP(p, q) do { \
        if ((a[p] & 7u) > (a[q] & 7u)) { unsigned _t = a[p]; a[p] = a[q]; a[q] = _t; } \
    } while (0)
    CSWP(0,1); CSWP(2,3); CSWP(4,5); CSWP(6,7);
    CSWP(0,2); CSWP(1,3); CSWP(4,6); CSWP(5,7);
    CSWP(1,2); CSWP(5,6);
    CSWP(0,4); CSWP(1,5); CSWP(2,6); CSWP(3,7);
    CSWP(2,4); CSWP(3,5);
    CSWP(1,2); CSWP(3,4); CSWP(5,6);
#undef CSWP

    // Rotate by k&7 (3 predicated barrel stages, static indices after unroll).
    int r = k & 7;
    #pragma unroll
    for (int st = 0; st < 3; st++) {
        int amt = 1 << st;
        if (r & amt) {
            unsigned tmp[8];
            #pragma unroll
            for (int j = 0; j < 8; j++) tmp[j] = a[(j + amt) & 7];
            #pragma unroll
            for (int j = 0; j < 8; j++) a[j] = tmp[j];
        }
    }

    uint4 w;
    w.x = a[0] | (a[1] << 16);
    w.y = a[2] | (a[3] << 16);
    w.z = a[4] | (a[5] << 16);
    w.w = a[6] | (a[7] << 16);
    ((uint4*)g_slot)[i] = w;   // coalesced: consecutive k -> consecutive 16B
}

static __device__ __forceinline__ unsigned hmul2u(unsigned a, unsigned b) {
    __half2 ha = *reinterpret_cast<__half2*>(&a);
    __half2 hb = *reinterpret_cast<__half2*>(&b);
    __half2 hr = __hmul2(ha, hb);
    return *reinterpret_cast<unsigned*>(&hr);
}
static __device__ __forceinline__ unsigned hmax2u(unsigned a, unsigned b) {
    __half2 ha = *reinterpret_cast<__half2*>(&a);
    __half2 hb = *reinterpret_cast<__half2*>(&b);
    __half2 hr = __hmax2(ha, hb);
    return *reinterpret_cast<unsigned*>(&hr);
}
static __device__ __forceinline__ uint4 mulh8(uint4 a, uint4 b) {
    a.x = hmul2u(a.x, b.x); a.y = hmul2u(a.y, b.y);
    a.z = hmul2u(a.z, b.z); a.w = hmul2u(a.w, b.w);
    return a;
}
static __device__ __forceinline__ uint4 maxh8(uint4 a, uint4 b) {
    a.x = hmax2u(a.x, b.x); a.y = hmax2u(a.y, b.y);
    a.z = hmax2u(a.z, b.z); a.w = hmax2u(a.w, b.w);
    return a;
}
static __device__ __forceinline__ unsigned pack2(float a, float b) {
    __half2 h = __floats2half2_rn(a, b);
    return *reinterpret_cast<unsigned*>(&h);
}

__global__ void __launch_bounds__(THREADS, 1)
dnf_kernel(const float* __restrict__ x, float* __restrict__ out) {
    extern __shared__ unsigned smem_u[];   // 128 KB: [2 var][4096 feat][4 u32]
    const int b0 = blockIdx.x * MB;

    // Phase A: f = tid stride THREADS (coalesced LDG); split-variant layout
    // -> both STS.128 conflict-free (16B lane stride).
    uint4* slots = (uint4*)smem_u;
    for (int f = threadIdx.x; f < NF; f += THREADS) {
        float v[MB];
        #pragma unroll
        for (int r = 0; r < MB; r++)
            v[r] = x[(size_t)(b0 + r) * NF + f];
        uint4 hx, hn;
        hx.x = pack2(v[0], v[1]);               hn.x = pack2(1.f - v[0], 1.f - v[1]);
        hx.y = pack2(v[2], v[3]);               hn.y = pack2(1.f - v[2], 1.f - v[3]);
        hx.z = pack2(v[4], v[5]);               hn.z = pack2(1.f - v[4], 1.f - v[5]);
        hx.w = pack2(v[6], v[7]);               hn.w = pack2(1.f - v[6], 1.f - v[7]);
        slots[f]      = hx;                     // variant 0: x
        slots[NF + f] = hn;                     // variant 1: 1-x
    }
    __syncthreads();

    const char* sb = (const char*)smem_u;
    const int k = threadIdx.x;                       // NK == THREADS
    const uint4* tab = (const uint4*)g_slot + k;     // tab[s*NK]

    uint4 ta = tab[0];                               // s   table
    uint4 tb = tab[NK];                              // s+1 table
    uint4 mx = make_uint4(0u, 0u, 0u, 0u);           // fp16 products >= 0

    #pragma unroll
    for (int s = 0; s < NS; s++) {
        int spre = s + 2 < NS - 1 ? s + 2 : NS - 1;  // prefetch s+2 (clamped)
        uint4 tn = tab[spre * NK];

        uint4 q0 = *(const uint4*)(sb + ((ta.x & 0xFFFFu) << 4));
        uint4 q1 = *(const uint4*)(sb + ((ta.x >> 16)     << 4));
        uint4 q2 = *(const uint4*)(sb + ((ta.y & 0xFFFFu) << 4));
        uint4 q3 = *(const uint4*)(sb + ((ta.y >> 16)     << 4));
        uint4 q4 = *(const uint4*)(sb + ((ta.z & 0xFFFFu) << 4));
        uint4 q5 = *(const uint4*)(sb + ((ta.z >> 16)     << 4));
        uint4 q6 = *(const uint4*)(sb + ((ta.w & 0xFFFFu) << 4));
        uint4 q7 = *(const uint4*)(sb + ((ta.w >> 16)     << 4));

        uint4 p = mulh8(mulh8(mulh8(q0, q1), mulh8(q2, q3)),
                        mulh8(mulh8(q4, q5), mulh8(q6, q7)));
        mx = maxh8(mx, p);
        ta = tb;
        tb = tn;
    }

    float2 r01 = __half22float2(*reinterpret_cast<__half2*>(&mx.x));
    float2 r23 = __half22float2(*reinterpret_cast<__half2*>(&mx.y));
    float2 r45 = __half22float2(*reinterpret_cast<__half2*>(&mx.z));
    float2 r67 = __half22float2(*reinterpret_cast<__half2*>(&mx.w));
    out[(size_t)(b0 + 0) * NK + k] = r01.x;
    out[(size_t)(b0 + 1) * NK + k] = r01.y;
    out[(size_t)(b0 + 2) * NK + k] = r23.x;
    out[(size_t)(b0 + 3) * NK + k] = r23.y;
    out[(size_t)(b0 + 4) * NK + k] = r45.x;
    out[(size_t)(b0 + 5) * NK + k] = r45.y;
    out[(size_t)(b0 + 6) * NK + k] = r67.x;
    out[(size_t)(b0 + 7) * NK + k] = r67.y;
}

extern "C" void kernel_launch(void* const* d_in, const int* in_sizes, int n_in,
                              void* d_out, int out_size) {
    const float* x  = (const float*)d_in[0];
    const int*   cf = (const int*)d_in[1];
    const int*   cs = (const int*)d_in[2];
    const int*   cc = (const int*)d_in[3];
    float* out = (float*)d_out;

    prep_kernel<<<(NS * NK + 255) / 256, 256>>>(cf, cs, cc);

    size_t smem_bytes = (size_t)NF * 2 * MB * sizeof(__half);  // 131072
    cudaFuncSetAttribute(dnf_kernel,
                         cudaFuncAttributeMaxDynamicSharedMemorySize,
                         (int)smem_bytes);
    dnf_kernel<<<NB / MB, THREADS, smem_bytes>>>(x, out);
}

// round 13
// speedup vs baseline: 7.8524x; 1.0291x over previous
#include <cuda_runtime.h>
#include <cuda_fp16.h>

#define NB 2048
#define NF 4096
#define NC 8192
#define NT 8
#define NK 1024
#define NS 8
#define MB 8            // batch rows per tile (fp16, 8 rows per 16B slot)
#define THREADS 512     // 2 k per thread; 2 CTAs/SM (64 KB smem each)
#define KPT 2

// 16-bit slot table, layout [s][k][t]: index = (s*NK + k)*NT + t.
// slot = feat | (sign>0 ? 0 : 0x1000); smem byte addr = (slot&0xFFF)*16.
// smem holds ONLY x ([feat][8 rows] fp16, 16 B/feat = 64 KB); the negative
// literal 1-x is synthesized per-use: lit = fma(m, x, c), m=±1, c={0,1}.
// Slots within each (k,s) group are shaped (sorted by bank group, rotated
// by k&7) to reduce LDS conflict phases.
__device__ unsigned short g_slot[NS * NK * NT];   // 128 KB

__global__ void prep_kernel(const int* __restrict__ conj_feat,
                            const int* __restrict__ conj_sign,
                            const int* __restrict__ class_conj) {
    int i = blockIdx.x * blockDim.x + threadIdx.x;   // i = s*NK + k (k fast)
    if (i >= NS * NK) return;
    int s = i >> 10;
    int k = i & (NK - 1);
    int c = class_conj[k * NS + s];

    const int4* fp = (const int4*)(conj_feat + (size_t)c * NT);
    const int4* sp = (const int4*)(conj_sign + (size_t)c * NT);
    int4 f0 = fp[0], f1 = fp[1];
    int4 s0 = sp[0], s1 = sp[1];

    unsigned a[8];
    a[0] = (unsigned)f0.x | (s0.x > 0 ? 0u : 0x1000u);
    a[1] = (unsigned)f0.y | (s0.y > 0 ? 0u : 0x1000u);
    a[2] = (unsigned)f0.z | (s0.z > 0 ? 0u : 0x1000u);
    a[3] = (unsigned)f0.w | (s0.w > 0 ? 0u : 0x1000u);
    a[4] = (unsigned)f1.x | (s1.x > 0 ? 0u : 0x1000u);
    a[5] = (unsigned)f1.y | (s1.y > 0 ? 0u : 0x1000u);
    a[6] = (unsigned)f1.z | (s1.z > 0 ? 0u : 0x1000u);
    a[7] = (unsigned)f1.w | (s1.w > 0 ? 0u : 0x1000u);

    // Batcher odd-even sort by bank group (feat & 7); static indices only.
#define CSWP(p, q) do { \
        if ((a[p] & 7u) > (a[q] & 7u)) { unsigned _t = a[p]; a[p] = a[q]; a[q] = _t; } \
    } while (0)
    CSWP(0,1); CSWP(2,3); CSWP(4,5); CSWP(6,7);
    CSWP(0,2); CSWP(1,3); CSWP(4,6); CSWP(5,7);
    CSWP(1,2); CSWP(5,6);
    CSWP(0,4); CSWP(1,5); CSWP(2,6); CSWP(3,7);
    CSWP(2,4); CSWP(3,5);
    CSWP(1,2); CSWP(3,4); CSWP(5,6);
#undef CSWP

    int r = k & 7;                       // rotate by k&7 (stratify per warp)
    #pragma unroll
    for (int st = 0; st < 3; st++) {
        int amt = 1 << st;
        if (r & amt) {
            unsigned tmp[8];
            #pragma unroll
            for (int j = 0; j < 8; j++) tmp[j] = a[(j + amt) & 7];
            #pragma unroll
            for (int j = 0; j < 8; j++) a[j] = tmp[j];
        }
    }

    uint4 w;
    w.x = a[0] | (a[1] << 16);
    w.y = a[2] | (a[3] << 16);
    w.z = a[4] | (a[5] << 16);
    w.w = a[6] | (a[7] << 16);
    ((uint4*)g_slot)[i] = w;
}

static __device__ __forceinline__ unsigned hfma2u(unsigned a, unsigned b, unsigned c) {
    __half2 ha = *reinterpret_cast<__half2*>(&a);
    __half2 hb = *reinterpret_cast<__half2*>(&b);
    __half2 hc = *reinterpret_cast<__half2*>(&c);
    __half2 hr = __hfma2(ha, hb, hc);
    return *reinterpret_cast<unsigned*>(&hr);
}
static __device__ __forceinline__ unsigned hmul2u(unsigned a, unsigned b) {
    __half2 ha = *reinterpret_cast<__half2*>(&a);
    __half2 hb = *reinterpret_cast<__half2*>(&b);
    __half2 hr = __hmul2(ha, hb);
    return *reinterpret_cast<unsigned*>(&hr);
}
static __device__ __forceinline__ unsigned hmax2u(unsigned a, unsigned b) {
    __half2 ha = *reinterpret_cast<__half2*>(&a);
    __half2 hb = *reinterpret_cast<__half2*>(&b);
    __half2 hr = __hmax2(ha, hb);
    return *reinterpret_cast<unsigned*>(&hr);
}
static __device__ __forceinline__ uint4 mulh8(uint4 a, uint4 b) {
    a.x = hmul2u(a.x, b.x); a.y = hmul2u(a.y, b.y);
    a.z = hmul2u(a.z, b.z); a.w = hmul2u(a.w, b.w);
    return a;
}
static __device__ __forceinline__ uint4 maxh8(uint4 a, uint4 b) {
    a.x = hmax2u(a.x, b.x); a.y = hmax2u(a.y, b.y);
    a.z = hmax2u(a.z, b.z); a.w = hmax2u(a.w, b.w);
    return a;
}
static __device__ __forceinline__ unsigned pack2(float a, float b) {
    __half2 h = __floats2half2_rn(a, b);
    return *reinterpret_cast<unsigned*>(&h);
}

// Load one literal's 8 rows and apply the sign: lit = fma(±1, x, {0,1}).
static __device__ __forceinline__ uint4 literal(const char* sb, unsigned v) {
    uint4 q = *(const uint4*)(sb + ((v & 0xFFFu) << 4));
    bool neg = (v & 0x1000u) != 0;
    unsigned m2 = neg ? 0xBC00BC00u : 0x3C003C00u;   // -1 or +1 (half2)
    unsigned c2 = neg ? 0x3C003C00u : 0x00000000u;   //  1 or  0 (half2)
    q.x = hfma2u(q.x, m2, c2);
    q.y = hfma2u(q.y, m2, c2);
    q.z = hfma2u(q.z, m2, c2);
    q.w = hfma2u(q.w, m2, c2);
    return q;
}

static __device__ __forceinline__ uint4 sgroup(const char* sb, uint4 t) {
    uint4 l0 = literal(sb, t.x & 0xFFFFu);
    uint4 l1 = literal(sb, t.x >> 16);
    uint4 l2 = literal(sb, t.y & 0xFFFFu);
    uint4 l3 = literal(sb, t.y >> 16);
    uint4 l4 = literal(sb, t.z & 0xFFFFu);
    uint4 l5 = literal(sb, t.z >> 16);
    uint4 l6 = literal(sb, t.w & 0xFFFFu);
    uint4 l7 = literal(sb, t.w >> 16);
    return mulh8(mulh8(mulh8(l0, l1), mulh8(l2, l3)),
                 mulh8(mulh8(l4, l5), mulh8(l6, l7)));
}

static __device__ __forceinline__ void store_k(float* out, int b0, int k, uint4 mx) {
    float2 r01 = __half22float2(*reinterpret_cast<__half2*>(&mx.x));
    float2 r23 = __half22float2(*reinterpret_cast<__half2*>(&mx.y));
    float2 r45 = __half22float2(*reinterpret_cast<__half2*>(&mx.z));
    float2 r67 = __half22float2(*reinterpret_cast<__half2*>(&mx.w));
    out[(size_t)(b0 + 0) * NK + k] = r01.x;
    out[(size_t)(b0 + 1) * NK + k] = r01.y;
    out[(size_t)(b0 + 2) * NK + k] = r23.x;
    out[(size_t)(b0 + 3) * NK + k] = r23.y;
    out[(size_t)(b0 + 4) * NK + k] = r45.x;
    out[(size_t)(b0 + 5) * NK + k] = r45.y;
    out[(size_t)(b0 + 6) * NK + k] = r67.x;
    out[(size_t)(b0 + 7) * NK + k] = r67.y;
}

__global__ void __launch_bounds__(THREADS, 2)
dnf_kernel(const float* __restrict__ x, float* __restrict__ out) {
    extern __shared__ unsigned smem_u[];   // 64 KB: [4096 feat][4 u32] (x only)
    const int b0 = blockIdx.x * MB;

    // Phase A: stage x only. f = tid stride (coalesced LDG); STS.128
    // conflict-free (16B lane stride).
    uint4* slots = (uint4*)smem_u;
    for (int f = threadIdx.x; f < NF; f += THREADS) {
        float v[MB];
        #pragma unroll
        for (int r = 0; r < MB; r++)
            v[r] = x[(size_t)(b0 + r) * NF + f];
        uint4 hx;
        hx.x = pack2(v[0], v[1]);
        hx.y = pack2(v[2], v[3]);
        hx.z = pack2(v[4], v[5]);
        hx.w = pack2(v[6], v[7]);
        slots[f] = hx;
    }
    __syncthreads();

    const char* sb = (const char*)smem_u;

    #pragma unroll
    for (int kk = 0; kk < KPT; kk++) {
        const int k = threadIdx.x + kk * THREADS;
        const uint4* tab = (const uint4*)g_slot + k;   // tab[s*NK]

        uint4 ta = tab[0];
        uint4 tb = tab[NK];
        uint4 mx = make_uint4(0u, 0u, 0u, 0u);         // products >= 0

        #pragma unroll
        for (int s = 0; s < NS; s++) {
            int spre = s + 2 < NS - 1 ? s + 2 : NS - 1;
            uint4 tn = tab[spre * NK];
            mx = maxh8(mx, sgroup(sb, ta));
            ta = tb;
            tb = tn;
        }
        store_k(out, b0, k, mx);
    }
}

extern "C" void kernel_launch(void* const* d_in, const int* in_sizes, int n_in,
                              void* d_out, int out_size) {
    const float* x  = (const float*)d_in[0];
    const int*   cf = (const int*)d_in[1];
    const int*   cs = (const int*)d_in[2];
    const int*   cc = (const int*)d_in[3];
    float* out = (float*)d_out;

    prep_kernel<<<(NS * NK + 255) / 256, 256>>>(cf, cs, cc);

    size_t smem_bytes = (size_t)NF * MB * sizeof(__half);  // 65536
    cudaFuncSetAttribute(dnf_kernel,
                         cudaFuncAttributeMaxDynamicSharedMemorySize,
                         (int)smem_bytes);
    dnf_kernel<<<NB / MB, THREADS, smem_bytes>>>(x, out);
}